// round 6
// baseline (speedup 1.0000x reference)
#include <cuda_runtime.h>
#include <stdint.h>

#define BATCH 4096
#define IN_F  2048
#define OUT_F 4096
#define WORDS (IN_F / 64)     // 32 u64 per row
#define ROWS_PER_BLK 8
#define MAXM 64               // per-block match cap (expected: 0)

// Scratch (allocation-free: __device__ globals). Only ~1 MB + 32 KB.
__device__ uint64_t g_pbits[(size_t)OUT_F * WORDS];
__device__ uint64_t g_psig[OUT_F];

// -----------------------------------------------------------------------------
// Kernel 1: pack weight rows. One warp per row; float4 loads, 4 ballots/iter.
// Bit order within packed words is a fixed permutation of element order,
// identical to the x packing in kernel 2, so packed-row equality <=>
// original-bit-row equality (exact).
// -----------------------------------------------------------------------------
__global__ __launch_bounds__(256) void fsu_wpack_kernel(
    const float* __restrict__ w,
    const float* __restrict__ rng)
{
    const int row  = (blockIdx.x * blockDim.x + threadIdx.x) >> 5;
    const int lane = threadIdx.x & 31;

    const float rv = __ldg(rng);
    const float4* src = reinterpret_cast<const float4*>(w + (size_t)row * IN_F);

    uint64_t sig = 0;
    uint64_t myword = 0;

    #pragma unroll
    for (int it = 0; it < IN_F / 128; ++it) {        // 16 iterations
        const float4 v = __ldg(src + it * 32 + lane);
        // BinGen/BSGen: prob=(w+1)*0.5; source=round(prob*256); bit = source > rng
        const bool b0 = (rintf((v.x + 1.0f) * 0.5f * 256.0f) > rv);
        const bool b1 = (rintf((v.y + 1.0f) * 0.5f * 256.0f) > rv);
        const bool b2 = (rintf((v.z + 1.0f) * 0.5f * 256.0f) > rv);
        const bool b3 = (rintf((v.w + 1.0f) * 0.5f * 256.0f) > rv);
        const uint32_t m0 = __ballot_sync(0xFFFFFFFFu, b0);
        const uint32_t m1 = __ballot_sync(0xFFFFFFFFu, b1);
        const uint32_t m2 = __ballot_sync(0xFFFFFFFFu, b2);
        const uint32_t m3 = __ballot_sync(0xFFFFFFFFu, b3);
        const uint64_t wa = (uint64_t)m0 | ((uint64_t)m1 << 32);
        const uint64_t wb = (uint64_t)m2 | ((uint64_t)m3 << 32);
        if (lane == 2 * it)     myword = wa;
        if (lane == 2 * it + 1) myword = wb;
        sig = sig * 0x9E3779B97F4A7C15ull + wa;
        sig = sig * 0x9E3779B97F4A7C15ull + wb;
    }

    g_pbits[(size_t)row * WORDS + lane] = myword;
    if (lane == 0) g_psig[row] = sig;
}

// -----------------------------------------------------------------------------
// Kernel 2: per block — pack 8 x rows into smem, brute-force sig compare
// against all 4096 psigs (L2-resident, 128 u64 compares/thread), then emit
// the block's 8 output rows (zero + verified matches). Full-chip, mem-bound.
// -----------------------------------------------------------------------------
__global__ __launch_bounds__(256) void fsu_xmatch_kernel(
    const float* __restrict__ x,
    float* __restrict__ out)
{
    __shared__ uint64_t s_xbits[ROWS_PER_BLK][WORDS];   // 2 KB
    __shared__ uint64_t s_xsig[ROWS_PER_BLK];
    __shared__ int s_nm;
    __shared__ int s_mrow[MAXM];
    __shared__ int s_mo[MAXM];

    const int tid  = threadIdx.x;
    const int wid  = tid >> 5;
    const int lane = tid & 31;
    const int b    = blockIdx.x * ROWS_PER_BLK + wid;

    if (tid == 0) s_nm = 0;

    // ---- pack this warp's x row (values are exactly 0.0 or 1.0) ----
    {
        const float4* src = reinterpret_cast<const float4*>(x + (size_t)b * IN_F);
        uint64_t sig = 0;
        uint64_t myword = 0;
        #pragma unroll
        for (int it = 0; it < IN_F / 128; ++it) {
            const float4 v = __ldg(src + it * 32 + lane);
            const uint32_t m0 = __ballot_sync(0xFFFFFFFFu, v.x > 0.5f);
            const uint32_t m1 = __ballot_sync(0xFFFFFFFFu, v.y > 0.5f);
            const uint32_t m2 = __ballot_sync(0xFFFFFFFFu, v.z > 0.5f);
            const uint32_t m3 = __ballot_sync(0xFFFFFFFFu, v.w > 0.5f);
            const uint64_t wa = (uint64_t)m0 | ((uint64_t)m1 << 32);
            const uint64_t wb = (uint64_t)m2 | ((uint64_t)m3 << 32);
            if (lane == 2 * it)     myword = wa;
            if (lane == 2 * it + 1) myword = wb;
            sig = sig * 0x9E3779B97F4A7C15ull + wa;
            sig = sig * 0x9E3779B97F4A7C15ull + wb;
        }
        s_xbits[wid][lane] = myword;
        if (lane == 0) s_xsig[wid] = sig;
    }
    __syncthreads();

    // ---- brute-force sig compare: 16 psigs/thread vs 8 row sigs ----
    {
        uint64_t xs[ROWS_PER_BLK];
        #pragma unroll
        for (int r = 0; r < ROWS_PER_BLK; ++r) xs[r] = s_xsig[r];

        #pragma unroll
        for (int k = 0; k < OUT_F / 256; ++k) {          // 16 iterations
            const int o = k * 256 + tid;
            const uint64_t ps = __ldg(&g_psig[o]);
            #pragma unroll
            for (int r = 0; r < ROWS_PER_BLK; ++r) {
                if (ps == xs[r]) {
                    // exact verification: full 2048-bit compare
                    bool eq = true;
                    const uint64_t* pb = &g_pbits[(size_t)o * WORDS];
                    #pragma unroll 8
                    for (int kk = 0; kk < WORDS; ++kk)
                        if (s_xbits[r][kk] != __ldg(pb + kk)) { eq = false; break; }
                    if (eq) {
                        const int idx = atomicAdd(&s_nm, 1);
                        if (idx < MAXM) { s_mrow[idx] = r; s_mo[idx] = o; }
                    }
                }
            }
        }
    }
    __syncthreads();

    // ---- emit this block's 8 output rows: zeros (float4 stream) ----
    {
        float4* outv = reinterpret_cast<float4*>(out) +
                       (size_t)blockIdx.x * ROWS_PER_BLK * (OUT_F / 4);
        const float4 z = make_float4(0.0f, 0.0f, 0.0f, 0.0f);
        #pragma unroll
        for (int k = 0; k < ROWS_PER_BLK * (OUT_F / 4) / 256; ++k)   // 32 stores
            outv[k * 256 + tid] = z;
    }
    __syncthreads();

    // ---- apply verified matches (expected count: 0) ----
    if (tid < s_nm && tid < MAXM) {
        const size_t row = (size_t)blockIdx.x * ROWS_PER_BLK + s_mrow[tid];
        out[row * OUT_F + s_mo[tid]] = 1.0f;
    }
}

extern "C" void kernel_launch(void* const* d_in, const int* in_sizes, int n_in,
                              void* d_out, int out_size)
{
    const float* x   = (const float*)d_in[0];
    const float* w   = (const float*)d_in[1];
    const float* rng = (const float*)d_in[2];
    float* out = (float*)d_out;

    fsu_wpack_kernel<<<OUT_F / 8, 256>>>(w, rng);            // 512 blocks
    fsu_xmatch_kernel<<<BATCH / ROWS_PER_BLK, 256>>>(x, out); // 512 blocks
}

// round 7
// speedup vs baseline: 1.9964x; 1.9964x over previous
#include <cuda_runtime.h>
#include <stdint.h>

#define BATCH 4096
#define IN_F  2048
#define OUT_F 4096
#define WORDS (IN_F / 64)     // 32 u64 per row
#define MROWS 32              // batch rows per match block

// Scratch (allocation-free: __device__ globals)
__device__ uint64_t g_xbits[(size_t)BATCH * WORDS];
__device__ uint64_t g_pbits[(size_t)OUT_F * WORDS];
__device__ uint64_t g_xsig[BATCH];
__device__ uint64_t g_psig[OUT_F];

// -----------------------------------------------------------------------------
// Kernel 1: fused pack + zero-fill (HBM-bound: 64 MB read + 64 MB write).
//   1024 blocks x 256 threads. Each block packs 8 rows (one warp per row)
//   AND zero-fills a 4096-float4 slice of the output.
//   Pack: float4 loads, 4 ballots/iter. Bit order within packed words is a
//   fixed permutation of element order, identical for x and path rows, so
//   packed-row equality <=> original-bit-row equality (exact).
// -----------------------------------------------------------------------------
__global__ __launch_bounds__(256) void fsu_pack_zero_kernel(
    const float* __restrict__ x,
    const float* __restrict__ w,
    const float* __restrict__ rng,
    float4* __restrict__ outv)
{
    // ---- zero-fill slice (pure store stream, overlaps with pack loads) ----
    {
        const float4 z = make_float4(0.0f, 0.0f, 0.0f, 0.0f);
        const int base = blockIdx.x * 4096;          // 4M float4 / 1024 blocks
        #pragma unroll
        for (int k = 0; k < 16; ++k)
            outv[base + k * 256 + threadIdx.x] = z;
    }

    // ---- pack 8 rows (one warp per row) ----
    const int gwarp = (blockIdx.x * blockDim.x + threadIdx.x) >> 5;
    const int lane  = threadIdx.x & 31;
    const bool isX  = gwarp < BATCH;
    const int row   = isX ? gwarp : (gwarp - BATCH);

    const float rv = __ldg(rng);
    const float4* src = reinterpret_cast<const float4*>(
        (isX ? (x + (size_t)row * IN_F) : (w + (size_t)row * IN_F)));

    uint64_t sig = 0;
    uint64_t myword = 0;

    #pragma unroll
    for (int it = 0; it < IN_F / 128; ++it) {        // 16 iterations
        const float4 v = __ldg(src + it * 32 + lane);
        bool b0, b1, b2, b3;
        if (isX) {
            b0 = (v.x > 0.5f); b1 = (v.y > 0.5f);
            b2 = (v.z > 0.5f); b3 = (v.w > 0.5f);
        } else {
            // BinGen/BSGen: prob=(w+1)*0.5; source=round(prob*256); bit = source > rng
            b0 = (rintf((v.x + 1.0f) * 0.5f * 256.0f) > rv);
            b1 = (rintf((v.y + 1.0f) * 0.5f * 256.0f) > rv);
            b2 = (rintf((v.z + 1.0f) * 0.5f * 256.0f) > rv);
            b3 = (rintf((v.w + 1.0f) * 0.5f * 256.0f) > rv);
        }
        const uint32_t m0 = __ballot_sync(0xFFFFFFFFu, b0);
        const uint32_t m1 = __ballot_sync(0xFFFFFFFFu, b1);
        const uint32_t m2 = __ballot_sync(0xFFFFFFFFu, b2);
        const uint32_t m3 = __ballot_sync(0xFFFFFFFFu, b3);
        const uint64_t wa = (uint64_t)m0 | ((uint64_t)m1 << 32);
        const uint64_t wb = (uint64_t)m2 | ((uint64_t)m3 << 32);
        if (lane == 2 * it)     myword = wa;
        if (lane == 2 * it + 1) myword = wb;
        sig = sig * 0x9E3779B97F4A7C15ull + wa;
        sig = sig * 0x9E3779B97F4A7C15ull + wb;
    }

    if (isX) {
        g_xbits[(size_t)row * WORDS + lane] = myword;
        if (lane == 0) g_xsig[row] = sig;
    } else {
        g_pbits[(size_t)row * WORDS + lane] = myword;
        if (lane == 0) g_psig[row] = sig;
    }
}

// Exact verification: full 2048-bit compare. Equal sigs alone is never
// trusted — collisions cannot produce wrong output.
__device__ __noinline__ bool fsu_full_cmp(int b, int o)
{
    const uint64_t* xb = &g_xbits[(size_t)b * WORDS];
    const uint64_t* pb = &g_pbits[(size_t)o * WORDS];
    #pragma unroll 8
    for (int k = 0; k < WORDS; ++k)
        if (__ldg(xb + k) != __ldg(pb + k)) return false;
    return true;
}

// -----------------------------------------------------------------------------
// Kernel 2: brute-force sig matrix compare. 128 blocks x 1024 threads.
// Block owns MROWS=32 batch rows; each thread scans 4 psigs against all 32
// xsigs (128 independent register compares, no dependent chains, no hash).
// Runs after kernel 1 on the stream, so out[] is already zeroed; verified
// matches (expected: none) are written directly.
// -----------------------------------------------------------------------------
__global__ __launch_bounds__(1024) void fsu_match_kernel(float* __restrict__ out)
{
    __shared__ uint64_t s_xsig[MROWS];
    const int tid   = threadIdx.x;
    const int bbase = blockIdx.x * MROWS;

    if (tid < MROWS) s_xsig[tid] = __ldg(&g_xsig[bbase + tid]);
    __syncthreads();

    uint64_t xs[MROWS];
    #pragma unroll
    for (int r = 0; r < MROWS; ++r) xs[r] = s_xsig[r];

    #pragma unroll
    for (int k = 0; k < OUT_F / 1024; ++k) {         // 4 psigs per thread
        const int o = k * 1024 + tid;
        const uint64_t ps = __ldg(&g_psig[o]);
        #pragma unroll
        for (int r = 0; r < MROWS; ++r) {
            if (ps == xs[r]) {
                const int b = bbase + r;
                if (fsu_full_cmp(b, o))
                    out[(size_t)b * OUT_F + o] = 1.0f;
            }
        }
    }
}

extern "C" void kernel_launch(void* const* d_in, const int* in_sizes, int n_in,
                              void* d_out, int out_size)
{
    const float* x   = (const float*)d_in[0];
    const float* w   = (const float*)d_in[1];
    const float* rng = (const float*)d_in[2];
    float* out = (float*)d_out;

    // (BATCH + OUT_F) warps = 8192 -> 1024 blocks of 8 warps; each block also
    // zero-fills 4096 float4 of the output.
    fsu_pack_zero_kernel<<<1024, 256>>>(x, w, rng,
                                        reinterpret_cast<float4*>(out));

    fsu_match_kernel<<<BATCH / MROWS, 1024>>>(out);  // 128 blocks
}